// round 2
// baseline (speedup 1.0000x reference)
#include <cuda_runtime.h>

// Shapes (fixed by problem)
#define B_   512
#define N_   225   // centers = HW
#define C_   256
#define V_   256
#define M_   225   // HW
#define OUTC 512

// d_out layout: mem_out [B,512,225] floats, then p [B,225,225] floats.

#define SA 132   // float2 per k-row of As2 (padded)
#define SB 132   // floats per k-row of Bs (padded; 132*4=528 is 16B-multiple)

typedef unsigned long long ull;

// Packed fp32x2 FMA (SASS FFMA2) — 2 fp32 FMAs per issue slot.
__device__ __forceinline__ void fma2(ull &d, ull a, ull b) {
    asm("fma.rn.f32x2 %0, %1, %2, %0;" : "+l"(d) : "l"(a), "l"(b));
}

// ---------------------------------------------------------------------------
// GEMM1: S[b,n,m] = (sum_c m_in[b,n,c]*q_in[b,c,m]) / 16 * mask(n,m)
// 128x128 tile, 256 threads, 8x8 micro-tile on packed f32x2.
// A tile stored DUPLICATED in smem: As2[k][n] = (a,a), so FMA2 operands need
// no pack/swap instructions.
// ---------------------------------------------------------------------------
__global__ __launch_bounds__(256, 2) void k_scores2(const float* __restrict__ m_in,
                                                    const float* __restrict__ q_in,
                                                    float* __restrict__ p)
{
    __shared__ float2 As2[16][SA];
    __shared__ float  Bs[16][SB];
    __shared__ float  PW[15];

    const int tid = threadIdx.x;
    if (tid < 15) { float v = 1.0f; for (int i = 0; i < tid; i++) v *= 0.92f; PW[tid] = v; }

    const int b  = blockIdx.z;
    const int n0 = blockIdx.y * 128;
    const int m0 = blockIdx.x * 128;
    const int tx = tid & 15, ty = tid >> 4;

    const float* A = m_in + (size_t)b * N_ * C_;   // [n][c], row stride 256
    const float* Q = q_in + (size_t)b * C_ * M_;   // [c][m], row stride 225

    ull acc[8][4];
    #pragma unroll
    for (int i = 0; i < 8; i++)
        #pragma unroll
        for (int j = 0; j < 4; j++) acc[i][j] = 0ull;

    const int na = n0 + (tid >> 1);          // A-load row
    const int kb = tid >> 4;                 // B-load k (0..15)
    const int mcol = (tid & 15) * 8;         // B-load col base within tile
    const int mb = m0 + mcol;

    for (int c0 = 0; c0 < C_; c0 += 16) {
        __syncthreads();
        // --- A: load 2 float4 along c, store transposed + duplicated ---
        #pragma unroll
        for (int j = 0; j < 2; j++) {
            const int kbase = (tid & 1) * 8 + j * 4;
            float4 v;
            if (na < N_) v = *(const float4*)(A + (size_t)na * C_ + c0 + kbase);
            else         v = make_float4(0.f, 0.f, 0.f, 0.f);
            const int nn = na - n0;
            As2[kbase + 0][nn] = make_float2(v.x, v.x);
            As2[kbase + 1][nn] = make_float2(v.y, v.y);
            As2[kbase + 2][nn] = make_float2(v.z, v.z);
            As2[kbase + 3][nn] = make_float2(v.w, v.w);
        }
        // --- B: scalar loads (q_in row stride 900B is not 16B aligned) ---
        const float* qrow = Q + (size_t)(c0 + kb) * M_;
        #pragma unroll
        for (int u = 0; u < 8; u++) {
            int m = mb + u;
            Bs[kb][mcol + u] = (m < M_) ? qrow[m] : 0.0f;
        }
        __syncthreads();

        #pragma unroll
        for (int k = 0; k < 16; k++) {
            const ulonglong2* ap = (const ulonglong2*)&As2[k][ty * 8];
            const ulonglong2* bp = (const ulonglong2*)&Bs[k][tx * 8];
            ulonglong2 a01 = ap[0], a23 = ap[1], a45 = ap[2], a67 = ap[3];
            ulonglong2 b01 = bp[0], b23 = bp[1];
            ull av[8] = {a01.x, a01.y, a23.x, a23.y, a45.x, a45.y, a67.x, a67.y};
            ull bv[4] = {b01.x, b01.y, b23.x, b23.y};
            #pragma unroll
            for (int i = 0; i < 8; i++)
                #pragma unroll
                for (int j = 0; j < 4; j++)
                    fma2(acc[i][j], av[i], bv[j]);
        }
    }

    const float invs = 0.0625f;   // 1/sqrt(256)
    #pragma unroll
    for (int i = 0; i < 8; i++) {
        int n = n0 + ty * 8 + i;
        if (n >= N_) continue;
        int xn = n / 15, yn = n % 15;
        float* row = p + ((size_t)b * N_ + n) * M_;
        #pragma unroll
        for (int j = 0; j < 4; j++) {
            float2 v = *(float2*)&acc[i][j];
            int m = m0 + tx * 8 + 2 * j;
            if (m < M_) {
                int xm = m / 15, ym = m % 15;
                int dx = xn - xm; dx = dx < 0 ? -dx : dx;
                int dy = yn - ym; dy = dy < 0 ? -dy : dy;
                row[m] = v.x * invs * PW[dx] * PW[dy];
            }
            if (m + 1 < M_) {
                int xm = (m + 1) / 15, ym = (m + 1) % 15;
                int dx = xn - xm; dx = dx < 0 ? -dx : dx;
                int dy = yn - ym; dy = dy < 0 ? -dy : dy;
                row[m + 1] = v.y * invs * PW[dx] * PW[dy];
            }
        }
    }
}

// ---------------------------------------------------------------------------
// Softmax over centers axis (n), in place on p[b,:,m].
// ---------------------------------------------------------------------------
__global__ __launch_bounds__(256) void k_softmax(float* __restrict__ p)
{
    const int b = blockIdx.x;
    const int m = threadIdx.x;
    if (m >= M_) return;
    float* col = p + (size_t)b * N_ * M_ + m;

    float mx = -1e30f;
    float s  = 0.0f;
    for (int n = 0; n < N_; n++) {
        float x = col[(size_t)n * M_];
        float nmx = fmaxf(mx, x);
        s = s * __expf(mx - nmx) + __expf(x - nmx);
        mx = nmx;
    }
    float inv = 1.0f / s;
    for (int n = 0; n < N_; n++) {
        float x = col[(size_t)n * M_];
        col[(size_t)n * M_] = __expf(x - mx) * inv;
    }
}

// ---------------------------------------------------------------------------
// GEMM2: mem[b,v,m] = sum_n m_out[b,n,v] * p[b,n,m]
// Both operands are k(=n)-slow; same 128x128 f32x2 structure.
// ---------------------------------------------------------------------------
__global__ __launch_bounds__(256, 2) void k_mem2(const float* __restrict__ m_out,
                                                 const float* __restrict__ p,
                                                 float* __restrict__ out)
{
    __shared__ float2 As2[16][SA];
    __shared__ float  Bs[16][SB];

    const int tid = threadIdx.x;
    const int b  = blockIdx.z;
    const int v0 = blockIdx.y * 128;
    const int m0 = blockIdx.x * 128;
    const int tx = tid & 15, ty = tid >> 4;

    const float* A = m_out + (size_t)b * N_ * V_;   // [n][v], row stride 256
    const float* P = p + (size_t)b * N_ * M_;       // [n][m], row stride 225

    ull acc[8][4];
    #pragma unroll
    for (int i = 0; i < 8; i++)
        #pragma unroll
        for (int j = 0; j < 4; j++) acc[i][j] = 0ull;

    const int kb = tid >> 4;
    const int cb = (tid & 15) * 8;

    for (int n0 = 0; n0 < N_; n0 += 16) {
        __syncthreads();
        const int n = n0 + kb;
        if (n < N_) {
            const float4* ar = (const float4*)(A + (size_t)n * V_ + v0 + cb);
            float4 v1 = ar[0], v2 = ar[1];
            As2[kb][cb + 0] = make_float2(v1.x, v1.x);
            As2[kb][cb + 1] = make_float2(v1.y, v1.y);
            As2[kb][cb + 2] = make_float2(v1.z, v1.z);
            As2[kb][cb + 3] = make_float2(v1.w, v1.w);
            As2[kb][cb + 4] = make_float2(v2.x, v2.x);
            As2[kb][cb + 5] = make_float2(v2.y, v2.y);
            As2[kb][cb + 6] = make_float2(v2.z, v2.z);
            As2[kb][cb + 7] = make_float2(v2.w, v2.w);
            const float* prow = P + (size_t)n * M_;
            #pragma unroll
            for (int u = 0; u < 8; u++) {
                int m = m0 + cb + u;
                Bs[kb][cb + u] = (m < M_) ? prow[m] : 0.0f;
            }
        } else {
            #pragma unroll
            for (int u = 0; u < 8; u++) {
                As2[kb][cb + u] = make_float2(0.f, 0.f);
                Bs[kb][cb + u] = 0.0f;
            }
        }
        __syncthreads();

        #pragma unroll
        for (int k = 0; k < 16; k++) {
            const ulonglong2* ap = (const ulonglong2*)&As2[k][ty * 8];
            const ulonglong2* bp = (const ulonglong2*)&Bs[k][tx * 8];
            ulonglong2 a01 = ap[0], a23 = ap[1], a45 = ap[2], a67 = ap[3];
            ulonglong2 b01 = bp[0], b23 = bp[1];
            ull av[8] = {a01.x, a01.y, a23.x, a23.y, a45.x, a45.y, a67.x, a67.y};
            ull bv[4] = {b01.x, b01.y, b23.x, b23.y};
            #pragma unroll
            for (int i = 0; i < 8; i++)
                #pragma unroll
                for (int j = 0; j < 4; j++)
                    fma2(acc[i][j], av[i], bv[j]);
        }
    }

    #pragma unroll
    for (int i = 0; i < 8; i++) {
        const int v = v0 + ty * 8 + i;            // always < 256
        float* row = out + ((size_t)b * OUTC + v) * M_;
        #pragma unroll
        for (int j = 0; j < 4; j++) {
            float2 val = *(float2*)&acc[i][j];
            int m = m0 + tx * 8 + 2 * j;
            if (m < M_)     row[m]     = val.x;
            if (m + 1 < M_) row[m + 1] = val.y;
        }
    }
}

// ---------------------------------------------------------------------------
// Concat copy: mem_out[:, 256:512, :] = q_out (float4, HBM-bound, done).
// ---------------------------------------------------------------------------
__global__ __launch_bounds__(256) void k_copy(const float4* __restrict__ q,
                                              float* __restrict__ out)
{
    const int TOT4 = (B_ * 256 * M_) / 4;   // 7372800
    int i = blockIdx.x * blockDim.x + threadIdx.x;
    if (i >= TOT4) return;
    int b = i / 14400;                       // 57600/4
    float4 v = q[i];
    *(float4*)(out + (size_t)(b + 1) * 57600 + (size_t)i * 4) = v;
}

// ---------------------------------------------------------------------------
extern "C" void kernel_launch(void* const* d_in, const int* in_sizes, int n_in,
                              void* d_out, int out_size)
{
    const float* m_in  = (const float*)d_in[0];
    const float* m_out = (const float*)d_in[1];
    const float* q_in  = (const float*)d_in[2];
    const float* q_out = (const float*)d_in[3];
    float* out = (float*)d_out;
    float* p   = out + (size_t)B_ * OUTC * M_;   // p region after mem_out

    dim3 g1(2, 2, B_);
    k_scores2<<<g1, 256>>>(m_in, q_in, p);
    k_softmax<<<B_, 256>>>(p);
    dim3 g2(2, 2, B_);
    k_mem2<<<g2, 256>>>(m_out, p, out);
    const int TOT4 = (B_ * 256 * M_) / 4;
    k_copy<<<(TOT4 + 255) / 256, 256>>>((const float4*)q_out, out);
}

// round 4
// speedup vs baseline: 1.5855x; 1.5855x over previous
#include <cuda_runtime.h>
#include <cuda_bf16.h>
#include <cstdint>

#define B_   512
#define NC   225
#define CK   256
#define MH   225
#define VD   256
#define OUTC 512

// p^T scratch, bf16 hi/lo packed pairs: [B][256 m][128 words(=256 n)]
__device__ uint32_t g_pt_hi[(size_t)B_ * 256 * 128];
__device__ uint32_t g_pt_lo[(size_t)B_ * 256 * 128];

// ---------------- helpers ----------------
__device__ __forceinline__ uint32_t smem_u32(const void* p) {
    uint32_t a;
    asm("{ .reg .u64 t; cvta.to.shared.u64 t, %1; cvt.u32.u64 %0, t; }" : "=r"(a) : "l"(p));
    return a;
}
__device__ __forceinline__ uint32_t pack_hi2(float a, float b, uint32_t& lo) {
    __nv_bfloat16 ha = __float2bfloat16(a), hb = __float2bfloat16(b);
    __nv_bfloat16 la = __float2bfloat16(a - __bfloat162float(ha));
    __nv_bfloat16 lb = __float2bfloat16(b - __bfloat162float(hb));
    lo = (uint32_t)__bfloat16_as_ushort(la) | ((uint32_t)__bfloat16_as_ushort(lb) << 16);
    return (uint32_t)__bfloat16_as_ushort(ha) | ((uint32_t)__bfloat16_as_ushort(hb) << 16);
}
__device__ __forceinline__ void ldm4(uint32_t* r, uint32_t addr) {
    asm volatile("ldmatrix.sync.aligned.m8n8.x4.shared.b16 {%0,%1,%2,%3}, [%4];"
                 : "=r"(r[0]), "=r"(r[1]), "=r"(r[2]), "=r"(r[3]) : "r"(addr));
}
__device__ __forceinline__ void mma16816(float* d, const uint32_t* a, uint32_t b0, uint32_t b1) {
    asm volatile("mma.sync.aligned.m16n8k16.row.col.f32.bf16.bf16.f32 "
                 "{%0,%1,%2,%3}, {%4,%5,%6,%7}, {%8,%9}, {%0,%1,%2,%3};"
                 : "+f"(d[0]), "+f"(d[1]), "+f"(d[2]), "+f"(d[3])
                 : "r"(a[0]), "r"(a[1]), "r"(a[2]), "r"(a[3]), "r"(b0), "r"(b1));
}
__device__ __forceinline__ int iabs(int x) { return x < 0 ? -x : x; }

// smem layout (both GEMMs): A[128][72]b16 hi/lo, B[256][72]b16 hi/lo, pitch 144B
#define AH_OFF 0
#define AL_OFF 18432
#define BH_OFF 36864
#define BL_OFF 73728
#define PWS_OFF 110592          // 36 floats
#define SMEM_SZ 110848

// =============================== GEMM1 =====================================
// D[m,n] = S^T = q^T * m_in^T, masked, softmax over n fused in epilogue.
__global__ __launch_bounds__(256, 1)
void k_g1(const float* __restrict__ q_in, const float* __restrict__ m_in,
          float* __restrict__ p_out)
{
    extern __shared__ char sm[];
    const uint32_t su = smem_u32(sm);
    const int tid = threadIdx.x, lane = tid & 31, w = tid >> 5;
    const int b = blockIdx.y, m0 = blockIdx.x * 128;

    float* PWS = (float*)(sm + PWS_OFF);
    if (tid < 36) {
        float v = 0.0625f;                       // fold 1/sqrt(256)
        for (int i = 0; i < tid; i++) v *= 0.92f;
        PWS[tid] = v;
    }

    const float* Aq = q_in + (size_t)b * CK * MH;   // [c][m]
    const float* Bm = m_in + (size_t)b * NC * CK;   // [n][c]

    float acc[32][4];
    #pragma unroll
    for (int i = 0; i < 32; i++) { acc[i][0] = acc[i][1] = acc[i][2] = acc[i][3] = 0.f; }

    const int g = lane >> 3, rr = lane & 7;
    const uint32_t a_base = su + AH_OFF + (uint32_t)((w * 16 + (g & 1) * 8 + rr) * 144 + (g >> 1) * 16);
    const uint32_t b_base = su + BH_OFF + (uint32_t)(((g & 1) * 8 + rr) * 144 + (g >> 1) * 16);

    for (int ch = 0; ch < 4; ch++) {
        const int c0 = ch * 64;
        __syncthreads();
        // A: q_in^T tile [128 m][64 c], split bf16 hi/lo
        #pragma unroll 8
        for (int i = 0; i < 32; i++) {
            int idx = tid + (i << 8);
            int mm = idx & 127, cc = idx >> 7, gm = m0 + mm;
            float f = (gm < MH) ? Aq[(size_t)(c0 + cc) * MH + gm] : 0.0f;
            __nv_bfloat16 h = __float2bfloat16(f);
            __nv_bfloat16 l = __float2bfloat16(f - __bfloat162float(h));
            *(__nv_bfloat16*)(sm + AH_OFF + mm * 144 + cc * 2) = h;
            *(__nv_bfloat16*)(sm + AL_OFF + mm * 144 + cc * 2) = l;
        }
        // B: m_in tile [256 n][64 c] (zero-pad n>=225)
        #pragma unroll 4
        for (int i = 0; i < 16; i++) {
            int idx = tid + (i << 8);
            int q4 = idx & 15, nn = idx >> 4;
            float4 v = make_float4(0.f, 0.f, 0.f, 0.f);
            if (nn < NC) v = *(const float4*)(Bm + (size_t)nn * CK + c0 + q4 * 4);
            uint32_t l01, l23;
            uint32_t h01 = pack_hi2(v.x, v.y, l01);
            uint32_t h23 = pack_hi2(v.z, v.w, l23);
            *(uint2*)(sm + BH_OFF + nn * 144 + q4 * 8) = make_uint2(h01, h23);
            *(uint2*)(sm + BL_OFF + nn * 144 + q4 * 8) = make_uint2(l01, l23);
        }
        __syncthreads();
        #pragma unroll
        for (int ks = 0; ks < 4; ks++) {
            uint32_t ah[4], al[4];
            ldm4(ah, a_base + ks * 32);
            ldm4(al, a_base + 18432 + ks * 32);
            #pragma unroll
            for (int j = 0; j < 16; j++) {
                uint32_t bh[4], bl[4];
                ldm4(bh, b_base + j * 2304 + ks * 32);
                ldm4(bl, b_base + 36864 + j * 2304 + ks * 32);
                mma16816(acc[2 * j],     ah, bh[0], bh[2]);
                mma16816(acc[2 * j],     ah, bl[0], bl[2]);
                mma16816(acc[2 * j],     al, bh[0], bh[2]);
                mma16816(acc[2 * j + 1], ah, bh[1], bh[3]);
                mma16816(acc[2 * j + 1], ah, bl[1], bl[3]);
                mma16816(acc[2 * j + 1], al, bh[1], bh[3]);
            }
        }
    }

    // ------------------ fused masked softmax over n (register) -------------
    const int l2 = lane & 3;
    const int mA = m0 + w * 16 + (lane >> 2);
    const int mB = mA + 8;
    const int xmA = mA / 15, ymA = mA - 15 * xmA;
    const int xmB = mB / 15, ymB = mB - 15 * xmB;

    float mxA = -1e30f, mxB = -1e30f;
    #pragma unroll
    for (int nt = 0; nt < 32; nt++) {
        #pragma unroll
        for (int c = 0; c < 2; c++) {
            int n = nt * 8 + 2 * l2 + c;
            int xn = n / 15, yn = n - 15 * xn;
            bool ok = (nt < 28) || (n < NC);
            float fA = PWS[iabs(xn - xmA) + iabs(yn - ymA)];
            float fB = PWS[iabs(xn - xmB) + iabs(yn - ymB)];
            float vA = ok ? acc[nt][c] * fA     : -1e30f;
            float vB = ok ? acc[nt][2 + c] * fB : -1e30f;
            acc[nt][c] = vA; acc[nt][2 + c] = vB;
            mxA = fmaxf(mxA, vA); mxB = fmaxf(mxB, vB);
        }
    }
    mxA = fmaxf(mxA, __shfl_xor_sync(0xFFFFFFFFu, mxA, 1));
    mxA = fmaxf(mxA, __shfl_xor_sync(0xFFFFFFFFu, mxA, 2));
    mxB = fmaxf(mxB, __shfl_xor_sync(0xFFFFFFFFu, mxB, 1));
    mxB = fmaxf(mxB, __shfl_xor_sync(0xFFFFFFFFu, mxB, 2));

    float sA = 0.f, sB = 0.f;
    #pragma unroll
    for (int nt = 0; nt < 32; nt++) {
        sA += __expf(acc[nt][0] - mxA) + __expf(acc[nt][1] - mxA);
        sB += __expf(acc[nt][2] - mxB) + __expf(acc[nt][3] - mxB);
    }
    sA += __shfl_xor_sync(0xFFFFFFFFu, sA, 1);
    sA += __shfl_xor_sync(0xFFFFFFFFu, sA, 2);
    sB += __shfl_xor_sync(0xFFFFFFFFu, sB, 1);
    sB += __shfl_xor_sync(0xFFFFFFFFu, sB, 2);
    const float invA = 1.0f / sA, invB = 1.0f / sB;

    uint32_t* ptha = g_pt_hi + ((size_t)b * 256 + mA) * 128;
    uint32_t* ptla = g_pt_lo + ((size_t)b * 256 + mA) * 128;
    uint32_t* pthb = g_pt_hi + ((size_t)b * 256 + mB) * 128;
    uint32_t* ptlb = g_pt_lo + ((size_t)b * 256 + mB) * 128;
    float* pbase = p_out + (size_t)b * NC * MH;

    #pragma unroll
    for (int nt = 0; nt < 32; nt++) {
        int n0 = nt * 8 + 2 * l2;
        float pA0 = __expf(acc[nt][0] - mxA) * invA;
        float pA1 = __expf(acc[nt][1] - mxA) * invA;
        float pB0 = __expf(acc[nt][2] - mxB) * invB;
        float pB1 = __expf(acc[nt][3] - mxB) * invB;
        uint32_t loA, hiA = pack_hi2(pA0, pA1, loA);
        uint32_t loB, hiB = pack_hi2(pB0, pB1, loB);
        ptha[nt * 4 + l2] = hiA; ptla[nt * 4 + l2] = loA;
        pthb[nt * 4 + l2] = hiB; ptlb[nt * 4 + l2] = loB;
        if (mA < MH) {
            if (n0 < NC)     pbase[(size_t)n0 * MH + mA] = pA0;
            if (n0 + 1 < NC) pbase[(size_t)(n0 + 1) * MH + mA] = pA1;
        }
        if (mB < MH) {
            if (n0 < NC)     pbase[(size_t)n0 * MH + mB] = pB0;
            if (n0 + 1 < NC) pbase[(size_t)(n0 + 1) * MH + mB] = pB1;
        }
    }
}

// =============================== GEMM2 =====================================
// D[m,v] = mem^T = p^T * m_out; A = pt (bf16 hi/lo scratch), B = m_out^T.
__global__ __launch_bounds__(256, 1)
void k_g2(const float* __restrict__ m_out, float* __restrict__ out)
{
    extern __shared__ char sm[];
    const uint32_t su = smem_u32(sm);
    const int tid = threadIdx.x, lane = tid & 31, w = tid >> 5;
    const int b = blockIdx.y, m0 = blockIdx.x * 128;

    const float* Bo = m_out + (size_t)b * NC * VD;   // [n][v]

    float acc[32][4];
    #pragma unroll
    for (int i = 0; i < 32; i++) { acc[i][0] = acc[i][1] = acc[i][2] = acc[i][3] = 0.f; }

    const int g = lane >> 3, rr = lane & 7;
    const uint32_t a_base = su + AH_OFF + (uint32_t)((w * 16 + (g & 1) * 8 + rr) * 144 + (g >> 1) * 16);
    const uint32_t b_base = su + BH_OFF + (uint32_t)(((g & 1) * 8 + rr) * 144 + (g >> 1) * 16);

    for (int ch = 0; ch < 4; ch++) {
        const int n0 = ch * 64;
        __syncthreads();
        // A: pt tile [128 m][64 n] (already split bf16, packed words)
        #pragma unroll
        for (int i = 0; i < 4; i++) {
            int idx = tid + (i << 8);
            int mm = idx >> 3, q = idx & 7;
            size_t gi = ((size_t)b * 256 + m0 + mm) * 128 + (n0 >> 1) + q * 4;
            uint4 h = *(const uint4*)&g_pt_hi[gi];
            uint4 l = *(const uint4*)&g_pt_lo[gi];
            *(uint4*)(sm + AH_OFF + mm * 144 + q * 16) = h;
            *(uint4*)(sm + AL_OFF + mm * 144 + q * 16) = l;
        }
        // B: m_out^T tile [256 v][64 n] (transpose + split)
        #pragma unroll 8
        for (int i = 0; i < 64; i++) {
            int idx = tid + (i << 8);
            int vv = idx & 255, nn = idx >> 8;
            float f = (n0 + nn < NC) ? Bo[(size_t)(n0 + nn) * VD + vv] : 0.0f;
            __nv_bfloat16 h = __float2bfloat16(f);
            __nv_bfloat16 l = __float2bfloat16(f - __bfloat162float(h));
            *(__nv_bfloat16*)(sm + BH_OFF + vv * 144 + nn * 2) = h;
            *(__nv_bfloat16*)(sm + BL_OFF + vv * 144 + nn * 2) = l;
        }
        __syncthreads();
        #pragma unroll
        for (int ks = 0; ks < 4; ks++) {
            uint32_t ah[4], al[4];
            ldm4(ah, a_base + ks * 32);
            ldm4(al, a_base + 18432 + ks * 32);
            #pragma unroll
            for (int j = 0; j < 16; j++) {
                uint32_t bh[4], bl[4];
                ldm4(bh, b_base + j * 2304 + ks * 32);
                ldm4(bl, b_base + 36864 + j * 2304 + ks * 32);
                mma16816(acc[2 * j],     ah, bh[0], bh[2]);
                mma16816(acc[2 * j],     ah, bl[0], bl[2]);
                mma16816(acc[2 * j],     al, bh[0], bh[2]);
                mma16816(acc[2 * j + 1], ah, bh[1], bh[3]);
                mma16816(acc[2 * j + 1], ah, bl[1], bl[3]);
                mma16816(acc[2 * j + 1], al, bh[1], bh[3]);
            }
        }
    }

    const int l2 = lane & 3;
    const int mA = m0 + w * 16 + (lane >> 2);
    const int mB = mA + 8;
    float* obase = out + (size_t)b * OUTC * MH;
    #pragma unroll
    for (int nt = 0; nt < 32; nt++) {
        int v0 = nt * 8 + 2 * l2;
        if (mA < MH) {
            obase[(size_t)v0 * MH + mA]       = acc[nt][0];
            obase[(size_t)(v0 + 1) * MH + mA] = acc[nt][1];
        }
        if (mB < MH) {
            obase[(size_t)v0 * MH + mB]       = acc[nt][2];
            obase[(size_t)(v0 + 1) * MH + mB] = acc[nt][3];
        }
    }
}

// ============================ concat copy ==================================
__global__ __launch_bounds__(256) void k_copy(const float4* __restrict__ q,
                                              float* __restrict__ out)
{
    const int TOT4 = (B_ * 256 * MH) / 4;
    int i = blockIdx.x * blockDim.x + threadIdx.x;
    if (i >= TOT4) return;
    int b = i / 14400;
    float4 v = q[i];
    *(float4*)(out + (size_t)(b + 1) * 57600 + (size_t)i * 4) = v;
}

// ---------------------------------------------------------------------------
extern "C" void kernel_launch(void* const* d_in, const int* in_sizes, int n_in,
                              void* d_out, int out_size)
{
    const float* m_in  = (const float*)d_in[0];
    const float* m_out = (const float*)d_in[1];
    const float* q_in  = (const float*)d_in[2];
    const float* q_out = (const float*)d_in[3];
    float* out = (float*)d_out;
    float* p   = out + (size_t)B_ * OUTC * MH;

    static int inited = 0;
    if (!inited) {
        cudaFuncSetAttribute(k_g1, cudaFuncAttributeMaxDynamicSharedMemorySize, SMEM_SZ);
        cudaFuncSetAttribute(k_g2, cudaFuncAttributeMaxDynamicSharedMemorySize, SMEM_SZ);
        inited = 1;
    }

    k_g1<<<dim3(2, B_), 256, SMEM_SZ>>>(q_in, m_in, p);
    k_g2<<<dim3(2, B_), 256, SMEM_SZ>>>(m_out, out);
    const int TOT4 = (B_ * 256 * MH) / 4;
    k_copy<<<(TOT4 + 255) / 256, 256>>>((const float4*)q_out, out);
}

// round 5
// speedup vs baseline: 2.3030x; 1.4525x over previous
#include <cuda_runtime.h>
#include <cuda_bf16.h>
#include <cstdint>

#define B_   512
#define NC   225
#define CK   256
#define MH   225
#define VD   256
#define OUTC 512

// p^T scratch, bf16 hi/lo packed pairs: [B][256 m][128 words(=256 n)]
__device__ uint32_t g_pt_hi[(size_t)B_ * 256 * 128];
__device__ uint32_t g_pt_lo[(size_t)B_ * 256 * 128];

// ---------------- helpers ----------------
__device__ __forceinline__ uint32_t smem_u32(const void* p) {
    uint32_t a;
    asm("{ .reg .u64 t; cvta.to.shared.u64 t, %1; cvt.u32.u64 %0, t; }" : "=r"(a) : "l"(p));
    return a;
}
__device__ __forceinline__ uint32_t pack_hi2(float a, float b, uint32_t& lo) {
    __nv_bfloat16 ha = __float2bfloat16(a), hb = __float2bfloat16(b);
    __nv_bfloat16 la = __float2bfloat16(a - __bfloat162float(ha));
    __nv_bfloat16 lb = __float2bfloat16(b - __bfloat162float(hb));
    lo = (uint32_t)__bfloat16_as_ushort(la) | ((uint32_t)__bfloat16_as_ushort(lb) << 16);
    return (uint32_t)__bfloat16_as_ushort(ha) | ((uint32_t)__bfloat16_as_ushort(hb) << 16);
}
__device__ __forceinline__ void ldm4(uint32_t* r, uint32_t addr) {
    asm volatile("ldmatrix.sync.aligned.m8n8.x4.shared.b16 {%0,%1,%2,%3}, [%4];"
                 : "=r"(r[0]), "=r"(r[1]), "=r"(r[2]), "=r"(r[3]) : "r"(addr));
}
__device__ __forceinline__ void mma16816(float* d, const uint32_t* a, uint32_t b0, uint32_t b1) {
    asm volatile("mma.sync.aligned.m16n8k16.row.col.f32.bf16.bf16.f32 "
                 "{%0,%1,%2,%3}, {%4,%5,%6,%7}, {%8,%9}, {%0,%1,%2,%3};"
                 : "+f"(d[0]), "+f"(d[1]), "+f"(d[2]), "+f"(d[3])
                 : "r"(a[0]), "r"(a[1]), "r"(a[2]), "r"(a[3]), "r"(b0), "r"(b1));
}
__device__ __forceinline__ int iabs(int x) { return x < 0 ? -x : x; }

// smem: per buffer (K=32 chunk, pitch 80B):
//   AH 128x80=10240 | AL 10240 | BH 256x80=20480 | BL 20480  => 61440
#define AL_O   10240
#define BH_O   20480
#define BL_O   40960
#define BUFSZ  61440
#define PW_O   122880            // 36 floats
#define RMX_O  123024            // 2*128 floats
#define RS_O   124048            // 2*128 floats
#define SM_G1  125072
#define SM_G2  122880

// =============================== GEMM1 =====================================
// D[m,n] = S^T, masked, softmax over n fused. 512 thr: warp = (mw 0..7, nh 0..1)
__global__ __launch_bounds__(512, 1)
void k_g1(const float* __restrict__ q_in, const float* __restrict__ m_in,
          float* __restrict__ p_out)
{
    extern __shared__ char sm[];
    const uint32_t su = smem_u32(sm);
    const int tid = threadIdx.x, lane = tid & 31, w = tid >> 5;
    const int mw = w & 7, nh = w >> 3;
    const int b = blockIdx.y, m0 = blockIdx.x * 128;

    float* PWS = (float*)(sm + PW_O);
    float* RMX = (float*)(sm + RMX_O);
    float* RS  = (float*)(sm + RS_O);
    if (tid < 36) {
        float v = 0.0625f;
        for (int i = 0; i < tid; i++) v *= 0.92f;
        PWS[tid] = v;
    }

    const float* Aq = q_in + (size_t)b * CK * MH;   // [c][m]
    const float* Bm = m_in + (size_t)b * NC * CK;   // [n][c]

    float acc[16][4];
    #pragma unroll
    for (int i = 0; i < 16; i++) { acc[i][0] = acc[i][1] = acc[i][2] = acc[i][3] = 0.f; }

    const int g = lane >> 3, rr = lane & 7;
    const uint32_t a_base = su + (uint32_t)((mw * 16 + (g & 1) * 8 + rr) * 80 + (g >> 1) * 16);
    const uint32_t b_base = su + BH_O + (uint32_t)((nh * 128 + (g & 1) * 8 + rr) * 80 + (g >> 1) * 16);

    // staging thread maps
    const int amm = tid & 127, acg = (tid >> 7) * 8;     // A: row m, 8 c's
    const int bnn = tid >> 1,  bc16 = (tid & 1) * 16;    // B: row n, 16 c's
    const int agm = m0 + amm;
    float fa[8], fb[16];

    auto LOAD = [&](int ch) {
        const int c0 = ch * 32;
        #pragma unroll
        for (int t = 0; t < 8; t++)
            fa[t] = (agm < MH) ? Aq[(size_t)(c0 + acg + t) * MH + agm] : 0.0f;
        if (bnn < NC) {
            const float* br = Bm + (size_t)bnn * CK + c0 + bc16;
            #pragma unroll
            for (int t = 0; t < 4; t++) *(float4*)(fb + 4 * t) = *(const float4*)(br + 4 * t);
        } else {
            #pragma unroll
            for (int t = 0; t < 16; t++) fb[t] = 0.0f;
        }
    };
    auto CVSTS = [&](int bo) {
        uint4 hv, lv;
        hv.x = pack_hi2(fa[0], fa[1], lv.x); hv.y = pack_hi2(fa[2], fa[3], lv.y);
        hv.z = pack_hi2(fa[4], fa[5], lv.z); hv.w = pack_hi2(fa[6], fa[7], lv.w);
        *(uint4*)(sm + bo + amm * 80 + acg * 2) = hv;
        *(uint4*)(sm + bo + AL_O + amm * 80 + acg * 2) = lv;
        #pragma unroll
        for (int half = 0; half < 2; half++) {
            uint4 h2, l2v;
            h2.x = pack_hi2(fb[8*half+0], fb[8*half+1], l2v.x);
            h2.y = pack_hi2(fb[8*half+2], fb[8*half+3], l2v.y);
            h2.z = pack_hi2(fb[8*half+4], fb[8*half+5], l2v.z);
            h2.w = pack_hi2(fb[8*half+6], fb[8*half+7], l2v.w);
            *(uint4*)(sm + bo + BH_O + bnn * 80 + bc16 * 2 + half * 16) = h2;
            *(uint4*)(sm + bo + BL_O + bnn * 80 + bc16 * 2 + half * 16) = l2v;
        }
    };
    auto MMA = [&](uint32_t bo) {
        #pragma unroll
        for (int ks = 0; ks < 2; ks++) {
            uint32_t ah[4], al[4];
            ldm4(ah, a_base + bo + ks * 32);
            ldm4(al, a_base + bo + AL_O + ks * 32);
            #pragma unroll
            for (int j = 0; j < 8; j++) {
                uint32_t bh[4], bl[4];
                ldm4(bh, b_base + bo + j * 1280 + ks * 32);
                ldm4(bl, b_base + bo + (BL_O - BH_O) + j * 1280 + ks * 32);
                mma16816(acc[2*j],   ah, bh[0], bh[2]);
                mma16816(acc[2*j],   ah, bl[0], bl[2]);
                mma16816(acc[2*j],   al, bh[0], bh[2]);
                mma16816(acc[2*j+1], ah, bh[1], bh[3]);
                mma16816(acc[2*j+1], ah, bl[1], bl[3]);
                mma16816(acc[2*j+1], al, bh[1], bh[3]);
            }
        }
    };

    LOAD(0); CVSTS(0);
    __syncthreads();
    for (int ch = 0; ch < 8; ch++) {
        if (ch < 7) LOAD(ch + 1);
        MMA((ch & 1) * BUFSZ);
        if (ch < 7) CVSTS(((ch + 1) & 1) * BUFSZ);
        __syncthreads();
    }

    // ---------------- fused masked softmax over n ----------------
    const int l2 = lane & 3;
    const int rA = mw * 16 + (lane >> 2), rB = rA + 8;
    const int mA = m0 + rA, mB = mA + 8;
    const int mAc = (mA < MH) ? mA : MH - 1, mBc = (mB < MH) ? mB : MH - 1;
    const int xmA = mAc / 15, ymA = mAc - 15 * xmA;
    const int xmB = mBc / 15, ymB = mBc - 15 * xmB;

    float mxA = -1e30f, mxB = -1e30f;
    #pragma unroll
    for (int nt = 0; nt < 16; nt++) {
        #pragma unroll
        for (int c = 0; c < 2; c++) {
            int n = nh * 128 + nt * 8 + 2 * l2 + c;
            int xn = n / 15, yn = n - 15 * xn;
            bool ok = n < NC;
            float vA = ok ? acc[nt][c]     * PWS[iabs(xn - xmA) + iabs(yn - ymA)] : -1e30f;
            float vB = ok ? acc[nt][2 + c] * PWS[iabs(xn - xmB) + iabs(yn - ymB)] : -1e30f;
            acc[nt][c] = vA; acc[nt][2 + c] = vB;
            mxA = fmaxf(mxA, vA); mxB = fmaxf(mxB, vB);
        }
    }
    mxA = fmaxf(mxA, __shfl_xor_sync(~0u, mxA, 1)); mxA = fmaxf(mxA, __shfl_xor_sync(~0u, mxA, 2));
    mxB = fmaxf(mxB, __shfl_xor_sync(~0u, mxB, 1)); mxB = fmaxf(mxB, __shfl_xor_sync(~0u, mxB, 2));
    if (l2 == 0) { RMX[nh * 128 + rA] = mxA; RMX[nh * 128 + rB] = mxB; }
    __syncthreads();
    mxA = fmaxf(RMX[rA], RMX[128 + rA]);
    mxB = fmaxf(RMX[rB], RMX[128 + rB]);

    float sA = 0.f, sB = 0.f;
    #pragma unroll
    for (int nt = 0; nt < 16; nt++) {
        sA += __expf(acc[nt][0] - mxA) + __expf(acc[nt][1] - mxA);
        sB += __expf(acc[nt][2] - mxB) + __expf(acc[nt][3] - mxB);
    }
    sA += __shfl_xor_sync(~0u, sA, 1); sA += __shfl_xor_sync(~0u, sA, 2);
    sB += __shfl_xor_sync(~0u, sB, 1); sB += __shfl_xor_sync(~0u, sB, 2);
    if (l2 == 0) { RS[nh * 128 + rA] = sA; RS[nh * 128 + rB] = sB; }
    __syncthreads();
    const float invA = 1.0f / (RS[rA] + RS[128 + rA]);
    const float invB = 1.0f / (RS[rB] + RS[128 + rB]);

    uint32_t* ptha = g_pt_hi + ((size_t)b * 256 + mA) * 128;
    uint32_t* ptla = g_pt_lo + ((size_t)b * 256 + mA) * 128;
    uint32_t* pthb = g_pt_hi + ((size_t)b * 256 + mB) * 128;
    uint32_t* ptlb = g_pt_lo + ((size_t)b * 256 + mB) * 128;
    float* pbase = p_out + (size_t)b * NC * MH;

    #pragma unroll
    for (int nt = 0; nt < 16; nt++) {
        int n0 = nh * 128 + nt * 8 + 2 * l2;
        float pA0 = __expf(acc[nt][0] - mxA) * invA;
        float pA1 = __expf(acc[nt][1] - mxA) * invA;
        float pB0 = __expf(acc[nt][2] - mxB) * invB;
        float pB1 = __expf(acc[nt][3] - mxB) * invB;
        uint32_t loA, hiA = pack_hi2(pA0, pA1, loA);
        uint32_t loB, hiB = pack_hi2(pB0, pB1, loB);
        int wd = nh * 64 + nt * 4 + l2;
        ptha[wd] = hiA; ptla[wd] = loA;
        pthb[wd] = hiB; ptlb[wd] = loB;
        if (mA < MH) {
            if (n0 < NC)     pbase[(size_t)n0 * MH + mA] = pA0;
            if (n0 + 1 < NC) pbase[(size_t)(n0 + 1) * MH + mA] = pA1;
        }
        if (mB < MH) {
            if (n0 < NC)     pbase[(size_t)n0 * MH + mB] = pB0;
            if (n0 + 1 < NC) pbase[(size_t)(n0 + 1) * MH + mB] = pB1;
        }
    }
}

// =============================== GEMM2 =====================================
// D[m,v] = p^T * m_out^T; A = pt scratch, B = m_out transposed in-kernel.
__global__ __launch_bounds__(512, 1)
void k_g2(const float* __restrict__ m_out, float* __restrict__ out)
{
    extern __shared__ char sm[];
    const uint32_t su = smem_u32(sm);
    const int tid = threadIdx.x, lane = tid & 31, w = tid >> 5;
    const int mw = w & 7, nh = w >> 3;
    const int b = blockIdx.y, m0 = blockIdx.x * 128;

    const float* Bo = m_out + (size_t)b * NC * VD;   // [n][v]

    float acc[16][4];
    #pragma unroll
    for (int i = 0; i < 16; i++) { acc[i][0] = acc[i][1] = acc[i][2] = acc[i][3] = 0.f; }

    const int g = lane >> 3, rr = lane & 7;
    const uint32_t a_base = su + (uint32_t)((mw * 16 + (g & 1) * 8 + rr) * 80 + (g >> 1) * 16);
    const uint32_t b_base = su + BH_O + (uint32_t)((nh * 128 + (g & 1) * 8 + rr) * 80 + (g >> 1) * 16);

    const int amm = tid >> 2, aq = tid & 3;          // A: one uint4 hi + lo
    const int bvv = tid & 255, bng = (tid >> 8) * 16; // B: 16 n's for one v
    uint4 ha, la;
    float fb[16];

    auto LOAD = [&](int ch) {
        size_t gi = ((size_t)b * 256 + m0 + amm) * 128 + ch * 16 + aq * 4;
        ha = *(const uint4*)&g_pt_hi[gi];
        la = *(const uint4*)&g_pt_lo[gi];
        const int n0 = ch * 32;
        #pragma unroll
        for (int t = 0; t < 16; t++) {
            int n = n0 + bng + t;
            fb[t] = (n < NC) ? Bo[(size_t)n * VD + bvv] : 0.0f;
        }
    };
    auto CVSTS = [&](int bo) {
        *(uint4*)(sm + bo + amm * 80 + aq * 16) = ha;
        *(uint4*)(sm + bo + AL_O + amm * 80 + aq * 16) = la;
        #pragma unroll
        for (int t = 0; t < 16; t += 2) {
            uint32_t lo, hi = pack_hi2(fb[t], fb[t + 1], lo);
            *(uint32_t*)(sm + bo + BH_O + bvv * 80 + (bng + t) * 2) = hi;
            *(uint32_t*)(sm + bo + BL_O + bvv * 80 + (bng + t) * 2) = lo;
        }
    };
    auto MMA = [&](uint32_t bo) {
        #pragma unroll
        for (int ks = 0; ks < 2; ks++) {
            uint32_t ah[4], al[4];
            ldm4(ah, a_base + bo + ks * 32);
            ldm4(al, a_base + bo + AL_O + ks * 32);
            #pragma unroll
            for (int j = 0; j < 8; j++) {
                uint32_t bh[4], bl[4];
                ldm4(bh, b_base + bo + j * 1280 + ks * 32);
                ldm4(bl, b_base + bo + (BL_O - BH_O) + j * 1280 + ks * 32);
                mma16816(acc[2*j],   ah, bh[0], bh[2]);
                mma16816(acc[2*j],   ah, bl[0], bl[2]);
                mma16816(acc[2*j],   al, bh[0], bh[2]);
                mma16816(acc[2*j+1], ah, bh[1], bh[3]);
                mma16816(acc[2*j+1], ah, bl[1], bl[3]);
                mma16816(acc[2*j+1], al, bh[1], bh[3]);
            }
        }
    };

    LOAD(0); CVSTS(0);
    __syncthreads();
    for (int ch = 0; ch < 8; ch++) {
        if (ch < 7) LOAD(ch + 1);
        MMA((ch & 1) * BUFSZ);
        if (ch < 7) CVSTS(((ch + 1) & 1) * BUFSZ);
        __syncthreads();
    }

    const int l2 = lane & 3;
    const int mA = m0 + mw * 16 + (lane >> 2);
    const int mB = mA + 8;
    float* obase = out + (size_t)b * OUTC * MH;
    #pragma unroll
    for (int nt = 0; nt < 16; nt++) {
        int v0 = nh * 128 + nt * 8 + 2 * l2;
        if (mA < MH) {
            obase[(size_t)v0 * MH + mA]       = acc[nt][0];
            obase[(size_t)(v0 + 1) * MH + mA] = acc[nt][1];
        }
        if (mB < MH) {
            obase[(size_t)v0 * MH + mB]       = acc[nt][2];
            obase[(size_t)(v0 + 1) * MH + mB] = acc[nt][3];
        }
    }
}

// ============================ concat copy ==================================
__global__ __launch_bounds__(256) void k_copy(const float4* __restrict__ q,
                                              float* __restrict__ out)
{
    const int TOT4 = (B_ * 256 * MH) / 4;
    int i = blockIdx.x * blockDim.x + threadIdx.x;
    if (i >= TOT4) return;
    int b = i / 14400;
    float4 v = q[i];
    *(float4*)(out + (size_t)(b + 1) * 57600 + (size_t)i * 4) = v;
}

// ---------------------------------------------------------------------------
extern "C" void kernel_launch(void* const* d_in, const int* in_sizes, int n_in,
                              void* d_out, int out_size)
{
    const float* m_in  = (const float*)d_in[0];
    const float* m_out = (const float*)d_in[1];
    const float* q_in  = (const float*)d_in[2];
    const float* q_out = (const float*)d_in[3];
    float* out = (float*)d_out;
    float* p   = out + (size_t)B_ * OUTC * MH;

    static int inited = 0;
    if (!inited) {
        cudaFuncSetAttribute(k_g1, cudaFuncAttributeMaxDynamicSharedMemorySize, SM_G1);
        cudaFuncSetAttribute(k_g2, cudaFuncAttributeMaxDynamicSharedMemorySize, SM_G2);
        inited = 1;
    }

    k_g1<<<dim3(2, B_), 512, SM_G1>>>(q_in, m_in, p);
    k_g2<<<dim3(2, B_), 512, SM_G2>>>(m_out, out);
    const int TOT4 = (B_ * 256 * MH) / 4;
    k_copy<<<(TOT4 + 255) / 256, 256>>>((const float4*)q_out, out);
}